// round 1
// baseline (speedup 1.0000x reference)
#include <cuda_runtime.h>

// SplitMLP: B=128, C=16, V=32, H=64, O=4, G=10000
//   h[b,g,j] = relu( day[b,:] @ W1_day[g,j,:] + items[b,g,:] @ W1_var[g,j,:] + b1[g,j] )
//   y[b,g,o] = h[b,g,:] @ W2[g,o,:] + b2[g,o]
// One CTA per group. fc1 as register-tiled 128x64x48 GEMM, fc2 fused via smem h.

#define NB 128   // batch
#define NC 16    // day features
#define NV 32    // item features
#define NH 64    // hidden
#define NO 4     // out per group
#define NG 10000 // groups
#define NK 48    // NC + NV
#define AP 48    // A tile row stride (floats)
#define WP 64    // W tile row stride
#define BP 132   // h (transposed) row stride, padded

__global__ __launch_bounds__(256, 2)
void splitmlp_kernel(const float* __restrict__ day,
                     const float* __restrict__ items,
                     const float* __restrict__ W1d,
                     const float* __restrict__ W1v,
                     const float* __restrict__ b1,
                     const float* __restrict__ W2,
                     const float* __restrict__ b2,
                     float* __restrict__ out)
{
    // Union region: A[128][48] + W[48][64] = 9216 floats during fc1,
    // reused as h_t[64][132] = 8448 floats for fc2.
    __shared__ float u[NB * AP + NK * WP];   // 9216 floats = 36 KB
    __shared__ float W2s[NO * NH];
    __shared__ float b1s[NH];
    __shared__ float b2s[NO];

    float* As = u;                 // [b][k], k-major rows
    float* Ws = u + NB * AP;       // [k][j]
    float* hs = u;                 // [j][b] (aliases As/Ws after sync)

    const int g = blockIdx.x;
    const int t = threadIdx.x;

    // ---------- Stage inputs to shared ----------
    // day -> As[b][0..15]   (512 float4 total)
    {
        const float4* src = (const float4*)day;
        #pragma unroll
        for (int i = 0; i < 2; i++) {
            int idx = t + i * 256;
            int b = idx >> 2, q = idx & 3;
            float4 v = src[idx];
            *(float4*)&As[b * AP + q * 4] = v;
        }
    }
    // items[b, g, :] -> As[b][16..47]  (1024 float4)
    {
        #pragma unroll
        for (int i = 0; i < 4; i++) {
            int idx = t + i * 256;
            int b = idx >> 3, q = idx & 7;
            float4 v = *(const float4*)&items[(size_t)b * NG * NV + (size_t)g * NV + q * 4];
            *(float4*)&As[b * AP + NC + q * 4] = v;
        }
    }
    // W1_day[g] (64x16) -> transposed Ws[c][j]
    {
        int j = t >> 2, q = (t & 3) * 4;
        float4 v = *(const float4*)&W1d[(size_t)g * NH * NC + j * NC + q];
        Ws[(q + 0) * WP + j] = v.x;
        Ws[(q + 1) * WP + j] = v.y;
        Ws[(q + 2) * WP + j] = v.z;
        Ws[(q + 3) * WP + j] = v.w;
    }
    // W1_var[g] (64x32) -> transposed Ws[16+v][j]
    {
        #pragma unroll
        for (int i = 0; i < 2; i++) {
            int idx = t + i * 256;
            int j = idx >> 3, q = (idx & 7) * 4;
            float4 v = *(const float4*)&W1v[(size_t)g * NH * NV + j * NV + q];
            Ws[(NC + q + 0) * WP + j] = v.x;
            Ws[(NC + q + 1) * WP + j] = v.y;
            Ws[(NC + q + 2) * WP + j] = v.z;
            Ws[(NC + q + 3) * WP + j] = v.w;
        }
    }
    // W2[g] (4x64), b1[g] (64), b2[g] (4)
    if (t < 64) {
        *(float4*)&W2s[t * 4] = *(const float4*)&W2[(size_t)g * NO * NH + t * 4];
    } else if (t < 128) {
        b1s[t - 64] = b1[(size_t)g * NH + (t - 64)];
    } else if (t < 132) {
        b2s[t - 128] = b2[(size_t)g * NO + (t - 128)];
    }
    __syncthreads();

    // ---------- fc1: 128x64x48 register-tiled GEMM ----------
    const int jt = t & 15, bt = t >> 4;
    const int j0 = jt * 4, b0 = bt * 8;

    float acc[8][4];
    #pragma unroll
    for (int bb = 0; bb < 8; bb++)
        #pragma unroll
        for (int jj = 0; jj < 4; jj++) acc[bb][jj] = 0.0f;

    #pragma unroll 4
    for (int k = 0; k < NK; k += 4) {
        float4 a[8], w[4];
        #pragma unroll
        for (int bb = 0; bb < 8; bb++) a[bb] = *(float4*)&As[(b0 + bb) * AP + k];
        #pragma unroll
        for (int kk = 0; kk < 4; kk++) w[kk] = *(float4*)&Ws[(k + kk) * WP + j0];
        #pragma unroll
        for (int kk = 0; kk < 4; kk++) {
            #pragma unroll
            for (int bb = 0; bb < 8; bb++) {
                float av = (kk == 0) ? a[bb].x : (kk == 1) ? a[bb].y : (kk == 2) ? a[bb].z : a[bb].w;
                acc[bb][0] += av * w[kk].x;
                acc[bb][1] += av * w[kk].y;
                acc[bb][2] += av * w[kk].z;
                acc[bb][3] += av * w[kk].w;
            }
        }
    }

    // All reads of As/Ws are complete for every thread before hs overwrites them.
    __syncthreads();

    // bias + relu, store h transposed: hs[j][b]
    #pragma unroll
    for (int jj = 0; jj < 4; jj++) {
        float bias = b1s[j0 + jj];
        float4 v0, v1;
        v0.x = fmaxf(acc[0][jj] + bias, 0.0f);
        v0.y = fmaxf(acc[1][jj] + bias, 0.0f);
        v0.z = fmaxf(acc[2][jj] + bias, 0.0f);
        v0.w = fmaxf(acc[3][jj] + bias, 0.0f);
        v1.x = fmaxf(acc[4][jj] + bias, 0.0f);
        v1.y = fmaxf(acc[5][jj] + bias, 0.0f);
        v1.z = fmaxf(acc[6][jj] + bias, 0.0f);
        v1.w = fmaxf(acc[7][jj] + bias, 0.0f);
        *(float4*)&hs[(j0 + jj) * BP + b0]     = v0;
        *(float4*)&hs[(j0 + jj) * BP + b0 + 4] = v1;
    }
    __syncthreads();

    // ---------- fc2: y[b,g,o] = h[b,:] @ W2[g,o,:] + b2 ----------
    if (t < NB) {
        const int b = t;
        float y0 = b2s[0], y1 = b2s[1], y2 = b2s[2], y3 = b2s[3];
        #pragma unroll
        for (int j = 0; j < NH; j++) {
            float hv = hs[j * BP + b];     // conflict-free: consecutive b per lane
            y0 += hv * W2s[0 * NH + j];    // W2s reads broadcast across the warp
            y1 += hv * W2s[1 * NH + j];
            y2 += hv * W2s[2 * NH + j];
            y3 += hv * W2s[3 * NH + j];
        }
        *(float4*)&out[(size_t)b * NG * NO + (size_t)g * NO] = make_float4(y0, y1, y2, y3);
    }
}

extern "C" void kernel_launch(void* const* d_in, const int* in_sizes, int n_in,
                              void* d_out, int out_size)
{
    const float* day   = (const float*)d_in[0];
    const float* items = (const float*)d_in[1];
    const float* W1d   = (const float*)d_in[2];
    const float* W1v   = (const float*)d_in[3];
    const float* b1    = (const float*)d_in[4];
    const float* W2    = (const float*)d_in[5];
    const float* b2    = (const float*)d_in[6];
    float* out = (float*)d_out;

    splitmlp_kernel<<<NG, 256>>>(day, items, W1d, W1v, b1, W2, b2, out);
}

// round 2
// speedup vs baseline: 1.2629x; 1.2629x over previous
#include <cuda_runtime.h>

// SplitMLP: B=128, C=16, V=32, H=64, O=4, G=10000
// Round 2: packed fp32 (fma.rn.f32x2) — 2 MACs per fma-pipe slot.
//   fc1: 128x64x48 GEMM, A transposed in smem so batch-pairs load as LDS.64.
//   fc2: o-pairs packed, W2 transposed in smem for mov-free ulonglong2 loads.

#define NB 128
#define NC 16
#define NV 32
#define NH 64
#define NO 4
#define NG 10000
#define NK 48
#define BP 130   // AsT / hs row stride (even, non-mult-of-32 banks offset)
#define WP 64

// d = a*b + c elementwise on packed {f32,f32}
#define FMA2(d, a, b, c) \
    asm("fma.rn.f32x2 %0, %1, %2, %3;" : "=l"(d) : "l"(a), "l"(b), "l"(c))
// replicate one float into both lanes
#define PACK2(d, x) \
    asm("mov.b64 %0, {%1, %1};" : "=l"(d) : "f"(x))
#define UNPACK2(lo, hi, v) \
    asm("mov.b64 {%0, %1}, %2;" : "=f"(lo), "=f"(hi) : "l"(v))

__global__ __launch_bounds__(256, 2)
void splitmlp_kernel(const float* __restrict__ day,
                     const float* __restrict__ items,
                     const float* __restrict__ W1d,
                     const float* __restrict__ W1v,
                     const float* __restrict__ b1,
                     const float* __restrict__ W2,
                     const float* __restrict__ b2,
                     float* __restrict__ out)
{
    // Union: AsT[48][130] (6240) + Ws[48][64] (3072) = 9312 floats during fc1,
    // reused as hs[64][130] (8320) for fc2.
    __shared__ float u[NK * BP + NK * WP];
    __shared__ __align__(16) float W2sT[NH * NO];  // [j][o]
    __shared__ float b1s[NH];
    __shared__ __align__(16) float b2s[NO];

    float* AsT = u;              // [k][b]
    float* Ws  = u + NK * BP;    // [k][j]
    float* hs  = u;              // [j][b] (aliases after sync)

    const int g = blockIdx.x;
    const int t = threadIdx.x;

    // ---------------- Stage inputs ----------------
    // day[b][c] -> AsT[c][b]
    {
        const float4* src = (const float4*)day;
        #pragma unroll
        for (int i = 0; i < 2; i++) {
            int idx = t + i * 256;
            int b = idx >> 2, q = idx & 3;
            float4 v = src[idx];
            AsT[(q * 4 + 0) * BP + b] = v.x;
            AsT[(q * 4 + 1) * BP + b] = v.y;
            AsT[(q * 4 + 2) * BP + b] = v.z;
            AsT[(q * 4 + 3) * BP + b] = v.w;
        }
    }
    // items[b][g][v] -> AsT[16+v][b]
    {
        #pragma unroll
        for (int i = 0; i < 4; i++) {
            int idx = t + i * 256;
            int b = idx >> 3, q = idx & 7;
            float4 v = *(const float4*)&items[(size_t)b * NG * NV + (size_t)g * NV + q * 4];
            AsT[(NC + q * 4 + 0) * BP + b] = v.x;
            AsT[(NC + q * 4 + 1) * BP + b] = v.y;
            AsT[(NC + q * 4 + 2) * BP + b] = v.z;
            AsT[(NC + q * 4 + 3) * BP + b] = v.w;
        }
    }
    // W1_day[g] (64x16) -> Ws[c][j]
    {
        int j = t >> 2, q = (t & 3) * 4;
        float4 v = *(const float4*)&W1d[(size_t)g * NH * NC + j * NC + q];
        Ws[(q + 0) * WP + j] = v.x;
        Ws[(q + 1) * WP + j] = v.y;
        Ws[(q + 2) * WP + j] = v.z;
        Ws[(q + 3) * WP + j] = v.w;
    }
    // W1_var[g] (64x32) -> Ws[16+v][j]
    {
        #pragma unroll
        for (int i = 0; i < 2; i++) {
            int idx = t + i * 256;
            int j = idx >> 3, q = (idx & 7) * 4;
            float4 v = *(const float4*)&W1v[(size_t)g * NH * NV + j * NV + q];
            Ws[(NC + q + 0) * WP + j] = v.x;
            Ws[(NC + q + 1) * WP + j] = v.y;
            Ws[(NC + q + 2) * WP + j] = v.z;
            Ws[(NC + q + 3) * WP + j] = v.w;
        }
    }
    // W2[g][o][j] -> W2sT[j][o];  b1, b2
    if (t < 64) {
        int o = t >> 4, jq = (t & 15) * 4;
        float4 v = *(const float4*)&W2[(size_t)g * NO * NH + o * NH + jq];
        W2sT[(jq + 0) * NO + o] = v.x;
        W2sT[(jq + 1) * NO + o] = v.y;
        W2sT[(jq + 2) * NO + o] = v.z;
        W2sT[(jq + 3) * NO + o] = v.w;
    } else if (t < 128) {
        b1s[t - 64] = b1[(size_t)g * NH + (t - 64)];
    } else if (t < 132) {
        b2s[t - 128] = b2[(size_t)g * NO + (t - 128)];
    }
    __syncthreads();

    // ---------------- fc1: packed-pair GEMM ----------------
    // 256 threads = 16 jt x 16 bt. Each thread: 4 b-pairs (8 batches) x 4 j.
    const int jt = t & 15, bt = t >> 4;
    const int j0 = jt * 4, b0 = bt * 8;

    unsigned long long acc[4][4];   // [b-pair][j]
    #pragma unroll
    for (int bp = 0; bp < 4; bp++)
        #pragma unroll
        for (int jj = 0; jj < 4; jj++) acc[bp][jj] = 0ULL;

    #pragma unroll 8
    for (int k = 0; k < NK; k++) {
        unsigned long long a2[4];
        #pragma unroll
        for (int bp = 0; bp < 4; bp++)
            a2[bp] = *(const unsigned long long*)&AsT[k * BP + b0 + 2 * bp];
        float4 wv = *(const float4*)&Ws[k * WP + j0];
        unsigned long long w2[4];
        PACK2(w2[0], wv.x);
        PACK2(w2[1], wv.y);
        PACK2(w2[2], wv.z);
        PACK2(w2[3], wv.w);
        #pragma unroll
        for (int bp = 0; bp < 4; bp++) {
            FMA2(acc[bp][0], a2[bp], w2[0], acc[bp][0]);
            FMA2(acc[bp][1], a2[bp], w2[1], acc[bp][1]);
            FMA2(acc[bp][2], a2[bp], w2[2], acc[bp][2]);
            FMA2(acc[bp][3], a2[bp], w2[3], acc[bp][3]);
        }
    }

    __syncthreads();   // all AsT/Ws reads complete before hs overwrites

    // bias + relu; store h transposed hs[j][b] as batch-pair float2
    #pragma unroll
    for (int jj = 0; jj < 4; jj++) {
        float bias = b1s[j0 + jj];
        #pragma unroll
        for (int bp = 0; bp < 4; bp++) {
            float lo, hi;
            UNPACK2(lo, hi, acc[bp][jj]);
            float2 st;
            st.x = fmaxf(lo + bias, 0.0f);
            st.y = fmaxf(hi + bias, 0.0f);
            *(float2*)&hs[(j0 + jj) * BP + b0 + 2 * bp] = st;
        }
    }
    __syncthreads();

    // ---------------- fc2: y[b] = h[b,:] @ W2^T + b2, o packed in pairs ----
    if (t < NB) {
        const int b = t;
        unsigned long long y01 = *(const unsigned long long*)&b2s[0];
        unsigned long long y23 = *(const unsigned long long*)&b2s[2];
        #pragma unroll
        for (int j = 0; j < NH; j++) {
            float hv = hs[j * BP + b];
            unsigned long long hv2;
            PACK2(hv2, hv);
            ulonglong2 w = *(const ulonglong2*)&W2sT[j * NO];  // {o0,o1},{o2,o3}
            FMA2(y01, hv2, w.x, y01);
            FMA2(y23, hv2, w.y, y23);
        }
        float4 res;
        UNPACK2(res.x, res.y, y01);
        UNPACK2(res.z, res.w, y23);
        *(float4*)&out[(size_t)b * NG * NO + (size_t)g * NO] = res;
    }
}

extern "C" void kernel_launch(void* const* d_in, const int* in_sizes, int n_in,
                              void* d_out, int out_size)
{
    const float* day   = (const float*)d_in[0];
    const float* items = (const float*)d_in[1];
    const float* W1d   = (const float*)d_in[2];
    const float* W1v   = (const float*)d_in[3];
    const float* b1    = (const float*)d_in[4];
    const float* W2    = (const float*)d_in[5];
    const float* b2    = (const float*)d_in[6];
    float* out = (float*)d_out;

    splitmlp_kernel<<<NG, 256>>>(day, items, W1d, W1v, b1, W2, b2, out);
}